// round 3
// baseline (speedup 1.0000x reference)
#include <cuda_runtime.h>
#include <cuda_bf16.h>
#include <stdint.h>

// Shapes (fixed):
//   updates: (8,128,128,256) float32 -> 33,554,432 elems
//   mask:    same shape int32 in [0, 16,777,216)
//   output:  (8,256,256,256) float32 -> 134,217,728 elems
// out[mask[i] + (i/4194304)*4194304] += updates[i]; rest zeros.
//
// Batch b scatters ONLY into chunks b..b+3 (chunk = 4,194,304 elems = 16 MB).
// Head = chunks 0..10 ([0, 46,137,344)); tail is never touched.
// Process batches sequentially so the active 67 MB window stays L2-resident.

#define CHUNK_ELEMS  4194304u
#define CHUNK_V4     (CHUNK_ELEMS / 4u)         // 1,048,576
#define BATCH_ELEMS  4194304u                   // updates per batch
#define BATCH_V4     (BATCH_ELEMS / 4u)         // 1,048,576 threads per kernel
#define OUT_ELEMS    134217728u
#define HEAD_ELEMS   46137344u                  // 11 chunks
#define HEAD_V4      (HEAD_ELEMS / 4u)          // 11,534,336
#define TAIL_V4      ((OUT_ELEMS - HEAD_ELEMS) / 4u)   // 22,020,096
#define TAIL_PER_K   (TAIL_V4 / 8u)             // 2,752,512 per batch kernel

__global__ __launch_bounds__(256, 8)
void scatter_batch_kernel(const float4* __restrict__ upd4,
                          const int4*  __restrict__ msk4,
                          float4* __restrict__ out4,
                          unsigned int batch)
{
    unsigned int i = blockIdx.x * 256u + threadIdx.x;   // [0, BATCH_V4)
    unsigned int g = batch * BATCH_V4 + i;

    // Streaming (evict-first) input loads: protect L2 for the atomic window.
    float4 u = __ldcs(upd4 + g);
    int4   m = __ldcs(msk4 + g);

    const float4 z = make_float4(0.f, 0.f, 0.f, 0.f);

    // Zero chunk (batch+4) for the NEXT batch (disjoint from this batch's
    // targets; sequential kernel launches order it before batch+1's atomics).
    // Plain store (not streaming) so it stays dirty in L2 for the next batch.
    if (batch < 7u)
        out4[(batch + 4u) * CHUNK_V4 + i] = z;

    // Zero this kernel's 1/8 share of the dead tail (streaming, evict-first).
    #pragma unroll
    for (unsigned int k = 0; k < 3; k++) {
        unsigned int t = i + k * BATCH_V4;
        if (t < TAIL_PER_K) __stcs(out4 + HEAD_V4 + batch * TAIL_PER_K + t, z);
    }

    // Scatter-add into chunks [batch, batch+4) — L2-resident window.
    unsigned int base = batch * CHUNK_ELEMS;
    float* out = (float*)out4;
    atomicAdd(out + base + (unsigned int)m.x, u.x);
    atomicAdd(out + base + (unsigned int)m.y, u.y);
    atomicAdd(out + base + (unsigned int)m.z, u.z);
    atomicAdd(out + base + (unsigned int)m.w, u.w);
}

extern "C" void kernel_launch(void* const* d_in, const int* in_sizes, int n_in,
                              void* d_out, int out_size)
{
    const float4* upd4 = (const float4*)d_in[0];
    const int4*   msk4 = (const int4*)d_in[1];

    // Zero chunks 0..3 (batch 0's window): 64 MB.
    cudaMemsetAsync(d_out, 0, (size_t)(4u * CHUNK_ELEMS) * sizeof(float), 0);

    const int threads = 256;
    const int blocks  = (int)(BATCH_V4 / threads);   // 4096
    for (unsigned int b = 0; b < 8; b++)
        scatter_batch_kernel<<<blocks, threads>>>(upd4, msk4, (float4*)d_out, b);
}

// round 4
// speedup vs baseline: 1.1629x; 1.1629x over previous
#include <cuda_runtime.h>
#include <cuda_bf16.h>
#include <stdint.h>

// Shapes (fixed):
//   updates: (8,128,128,256) float32 -> 33,554,432 elems
//   mask:    same shape int32 in [0, 16,777,216)
//   output:  (8,256,256,256) float32 -> 134,217,728 elems (512 MB)
// out[mask[i] + (i>>22)<<22] += updates[i]; rest zeros.
// Scatter region = [0, 46,137,344) elems (184 MB). Tail (352 MB) untouched.
//
// Strategy: two L2-resident window passes.
//   W0 = [0, 23,068,672)  (92 MB), W1 = [23,068,672, 46,137,344) (92 MB).
//   memset(W) -> scatter pass (atomics only for idx in W; window stays in L2,
//   atomics hit dirty lines, no DRAM RMW) -> next window -> zero tail last.

#define N_ELEMS      33554432u
#define N_VEC4       (N_ELEMS / 4u)             // 8,388,608
#define BATCH_V4_SH  20
#define BATCH_OFF_SH 22
#define SCATTER_END  46137344u                  // exclusive end of scatter region
#define W_SPLIT      23068672u                  // window boundary (elems)
#define OUT_ELEMS    134217728u
#define TAIL_START_V4 (SCATTER_END / 4u)        // 11,534,336
#define TAIL_V4      ((OUT_ELEMS - SCATTER_END) / 4u)  // 22,020,096

__global__ __launch_bounds__(256, 8)
void scatter_pass_kernel(const float4* __restrict__ upd4,
                         const int4*  __restrict__ msk4,
                         float* __restrict__ out,
                         unsigned int wlo, unsigned int whi)
{
    unsigned int i = blockIdx.x * 256u + threadIdx.x;   // [0, N_VEC4)

    float4 u = __ldcs(upd4 + i);
    int4   m = __ldcs(msk4 + i);

    unsigned int base = (i >> BATCH_V4_SH) << BATCH_OFF_SH;

    unsigned int ix = base + (unsigned int)m.x;
    unsigned int iy = base + (unsigned int)m.y;
    unsigned int iz = base + (unsigned int)m.z;
    unsigned int iw = base + (unsigned int)m.w;

    // Only touch addresses inside the current L2-resident window.
    if (ix >= wlo && ix < whi) atomicAdd(out + ix, u.x);
    if (iy >= wlo && iy < whi) atomicAdd(out + iy, u.y);
    if (iz >= wlo && iz < whi) atomicAdd(out + iz, u.z);
    if (iw >= wlo && iw < whi) atomicAdd(out + iw, u.w);
}

__global__ __launch_bounds__(256, 8)
void zero_tail_kernel(float4* __restrict__ out4)
{
    unsigned int i = blockIdx.x * 256u + threadIdx.x;
    const float4 z = make_float4(0.f, 0.f, 0.f, 0.f);
    #pragma unroll
    for (unsigned int k = 0; k < 3; k++) {
        unsigned int t = i + k * N_VEC4;
        if (t < TAIL_V4) __stcs(out4 + TAIL_START_V4 + t, z);
    }
}

extern "C" void kernel_launch(void* const* d_in, const int* in_sizes, int n_in,
                              void* d_out, int out_size)
{
    const float4* upd4 = (const float4*)d_in[0];
    const int4*   msk4 = (const int4*)d_in[1];
    float* out = (float*)d_out;

    const int threads = 256;
    const int blocks  = (int)(N_VEC4 / threads);   // 32768

    // Window 0: zero then scatter (atomics hit freshly-dirty L2 lines).
    cudaMemsetAsync(out, 0, (size_t)W_SPLIT * sizeof(float), 0);
    scatter_pass_kernel<<<blocks, threads>>>(upd4, msk4, out, 0u, W_SPLIT);

    // Window 1.
    cudaMemsetAsync(out + W_SPLIT, 0,
                    (size_t)(SCATTER_END - W_SPLIT) * sizeof(float), 0);
    scatter_pass_kernel<<<blocks, threads>>>(upd4, msk4, out, W_SPLIT, SCATTER_END);

    // Dead tail: pure streaming zero-fill, last so it can't pollute L2.
    zero_tail_kernel<<<blocks, threads>>>((float4*)d_out);
}